// round 7
// baseline (speedup 1.0000x reference)
#include <cuda_runtime.h>
#include <cuda_bf16.h>
#include <cstdint>

#define N_MSG 16384
#define NNB 10
#define IN_F 135
#define KQ 192            // padded fmess K (multiple of 32)
#define H 256
#define HEADS 4
#define DEPTH 5
#define NEG_INF -1e18f

// ---------------- fp32 state ------------------------------------------------
__device__ float g_h[N_MSG * H];
__device__ float g_KV[N_MSG * 2 * H];
__device__ float g_sumh[N_MSG * H];
__device__ float g_z[N_MSG * H];
__device__ float g_F[N_MSG * 3 * H];
__device__ float g_P[N_MSG * H];
__device__ float g_qs[N_MSG * HEADS];
__device__ float g_ks[N_MSG * HEADS];
__device__ float g_rowsum[N_MSG];
// ---------------- bf16 hi/lo GEMM operands ----------------------------------
__device__ __align__(16) __nv_bfloat16 g_h16h[N_MSG * H], g_h16l[N_MSG * H];
__device__ __align__(16) __nv_bfloat16 g_sh16h[N_MSG * H], g_sh16l[N_MSG * H];
__device__ __align__(16) __nv_bfloat16 g_rs16h[N_MSG * H], g_rs16l[N_MSG * H];
__device__ __align__(16) __nv_bfloat16 g_f16h[N_MSG * KQ], g_f16l[N_MSG * KQ];
__device__ __align__(16) __nv_bfloat16 g_Wkvh[512 * H], g_Wkvl[512 * H];
__device__ __align__(16) __nv_bfloat16 g_Wzrh[512 * H], g_Wzrl[512 * H];
__device__ __align__(16) __nv_bfloat16 g_Wh2h[H * H], g_Wh2l[H * H];
__device__ __align__(16) __nv_bfloat16 g_Wpreh[1024 * KQ], g_Wprel[1024 * KQ];
__device__ float g_bkv[512];
__device__ float g_bpre[1024];

// ---------------- helpers ----------------------------------------------------
__device__ __forceinline__ void split_bf16(float x, __nv_bfloat16& hi, __nv_bfloat16& lo) {
    hi = __float2bfloat16(x);
    lo = __float2bfloat16(x - __bfloat162float(hi));
}
__device__ __forceinline__ float sigmoidf_(float x) { return 1.0f / (1.0f + expf(-x)); }

__device__ __forceinline__ uint32_t smem_u32(const void* p) {
    uint32_t a;
    asm("{ .reg .u64 t; cvta.to.shared.u64 t, %1; cvt.u32.u64 %0, t; }" : "=r"(a) : "l"(p));
    return a;
}
__device__ __forceinline__ void ldsm_x4(uint32_t& r0, uint32_t& r1, uint32_t& r2,
                                        uint32_t& r3, uint32_t addr) {
    asm volatile("ldmatrix.sync.aligned.m8n8.x4.shared.b16 {%0,%1,%2,%3}, [%4];"
                 : "=r"(r0), "=r"(r1), "=r"(r2), "=r"(r3) : "r"(addr));
}
__device__ __forceinline__ void mma16816(float* d, const uint32_t* a, const uint32_t* b) {
    asm volatile(
        "mma.sync.aligned.m16n8k16.row.col.f32.bf16.bf16.f32 "
        "{%0,%1,%2,%3}, {%4,%5,%6,%7}, {%8,%9}, {%0,%1,%2,%3};"
        : "+f"(d[0]), "+f"(d[1]), "+f"(d[2]), "+f"(d[3])
        : "r"(a[0]), "r"(a[1]), "r"(a[2]), "r"(a[3]), "r"(b[0]), "r"(b[1]));
}
#define CP16(dst, src) \
    asm volatile("cp.async.cg.shared.global [%0], [%1], 16;" :: "r"(dst), "l"(src))
#define CP_COMMIT() asm volatile("cp.async.commit_group;" ::: "memory")
#define CP_WAIT(n)  asm volatile("cp.async.wait_group %0;" :: "n"(n) : "memory")

// ---------------- pad/split fmess -------------------------------------------
__global__ void pad_fmess(const float* __restrict__ fmess) {
    int i = blockIdx.x * blockDim.x + threadIdx.x;
    if (i >= N_MSG * KQ) return;
    int n = i / KQ, c = i % KQ;
    float x = (c < IN_F) ? fmess[n * IN_F + c] : 0.0f;
    split_bf16(x, g_f16h[i], g_f16l[i]);
}

// ---------------- weight packing --------------------------------------------
__global__ void pack_all(const float* __restrict__ Wq, const float* __restrict__ bq,
                         const float* __restrict__ Wk, const float* __restrict__ bk,
                         const float* __restrict__ Wv, const float* __restrict__ bv,
                         const float* __restrict__ Wz, const float* __restrict__ bz,
                         const float* __restrict__ Wr, const float* __restrict__ Ur,
                         const float* __restrict__ bur,
                         const float* __restrict__ Wh, const float* __restrict__ bh) {
    int i = blockIdx.x * blockDim.x + threadIdx.x;
    const int WIDE = IN_F + H;  // 391
    if (i < 512 * H) {
        int n = i / H, k = i % H;
        float kv = (n < H) ? Wk[n * H + k] : Wv[(n - H) * H + k];
        split_bf16(kv, g_Wkvh[i], g_Wkvl[i]);
        float zr = (n < H) ? Wz[n * WIDE + IN_F + k] : Ur[(n - H) * H + k];
        split_bf16(zr, g_Wzrh[i], g_Wzrl[i]);
    }
    if (i < H * H) {
        int n = i / H, k = i % H;
        split_bf16(Wh[n * WIDE + IN_F + k], g_Wh2h[i], g_Wh2l[i]);
    }
    if (i < 1024 * KQ) {
        int n = i / KQ, k = i % KQ;
        float v = 0.0f;
        if (k < IN_F) {
            if (n < 256) v = Wz[n * WIDE + k];
            else if (n < 512) v = Wr[(n - 256) * IN_F + k];
            else if (n < 768) v = Wh[(n - 512) * WIDE + k];
            else v = Wq[(n - 768) * IN_F + k];
        }
        split_bf16(v, g_Wpreh[i], g_Wprel[i]);
    }
    if (i < 512) g_bkv[i] = (i < 256) ? bk[i] : bv[i - 256];
    if (i < 1024) {
        float b = (i < 256) ? bz[i] : (i < 512) ? bur[i - 256]
                : (i < 768) ? bh[i - 512] : bq[i - 768];
        g_bpre[i] = b;
    }
}

// ---------------- mma.sync GEMM: 128x128 tile, 3-term split-bf16 -------------
// 4-stage cp.async pipeline + register-level fragment pipelining.
#define GT_PRE 0
#define GT_KV 1
#define GT_ZR 2
#define GT_FINAL 3
#define STR 40                  // padded smem row stride (bf16); conflict-free
#define STAGEB (128 * STR * 2)  // 10240 bytes per stage per operand
#define SMEM_DYN (8 * STAGEB)   // 4 stages x (A + B)

__global__ __launch_bounds__(256, 2)
void gemm_mma(const __nv_bfloat16* __restrict__ Ah, const __nv_bfloat16* __restrict__ Al,
              const __nv_bfloat16* __restrict__ Bh, const __nv_bfloat16* __restrict__ Bl,
              const float* __restrict__ bias, int Kp, int mode, float* __restrict__ dst) {
    extern __shared__ __nv_bfloat16 dsm[];
    const uint32_t sA0 = smem_u32(dsm);
    const uint32_t sB0 = sA0 + 4 * STAGEB;

    const int tid = threadIdx.x, lane = tid & 31, wid = tid >> 5;
    const int wm = (wid & 1) * 64, wn = (wid >> 1) * 32;
    const int row0 = blockIdx.y * 128, col0 = blockIdx.x * 128;

    // ldmatrix per-lane offsets
    const int arow = wm + (lane & 15), ak = (lane >> 4) << 3;
    const int g = lane >> 3;
    const int brow = wn + ((g >> 1) << 3) + (lane & 7), bk = (g & 1) << 3;
    const uint32_t aoff_l = (uint32_t)(arow * STR + ak) * 2;
    const uint32_t boff_l = (uint32_t)(brow * STR + bk) * 2;

    const int cpp = Kp >> 5;        // 32-wide chunks per phase
    const int NC = 3 * cpp;

    auto seg = [&](int c, const __nv_bfloat16*& Aseg, const __nv_bfloat16*& Bseg, int& kk) {
        int p = c / cpp;
        kk = (c - p * cpp) << 5;
        Aseg = (p < 2) ? Ah : Al;   // [hi, hi, lo]
        Bseg = (p == 1) ? Bl : Bh;  // [hi, lo, hi]
    };
    auto issue = [&](int c) {
        const __nv_bfloat16 *Aseg, *Bseg; int kk;
        seg(c, Aseg, Bseg, kk);
        const uint32_t abase = sA0 + (uint32_t)(c & 3) * STAGEB;
        const uint32_t bbase = sB0 + (uint32_t)(c & 3) * STAGEB;
#pragma unroll
        for (int i = 0; i < 2; i++) {
            int t2 = tid + (i << 8);
            int row = t2 >> 2, coli = (t2 & 3) << 3;
            uint32_t so = (uint32_t)(row * STR + coli) * 2;
            CP16(abase + so, Aseg + (size_t)(row0 + row) * Kp + kk + coli);
            CP16(bbase + so, Bseg + (size_t)(col0 + row) * Kp + kk + coli);
        }
        CP_COMMIT();
    };

    float acc[4][4][4];
#pragma unroll
    for (int i = 0; i < 4; i++)
#pragma unroll
        for (int j = 0; j < 4; j++)
#pragma unroll
            for (int q = 0; q < 4; q++) acc[i][j][q] = 0.f;

    issue(0); issue(1); issue(2);

    for (int c = 0; c < NC; c++) {
        const int allowed = NC - 1 - c;
        if (allowed >= 2)      CP_WAIT(2);
        else if (allowed == 1) CP_WAIT(1);
        else                   CP_WAIT(0);
        __syncthreads();
        if (c + 3 < NC) issue(c + 3);

        const uint32_t abase = sA0 + (uint32_t)(c & 3) * STAGEB + aoff_l;
        const uint32_t bbase = sB0 + (uint32_t)(c & 3) * STAGEB + boff_l;

        // ---- register-pipelined fragment schedule ----
        uint32_t a0[4][4], a1[4][4], b0[4][2], b1[4][2];
        // A(k0), B(k0), B(k1) upfront
#pragma unroll
        for (int mt = 0; mt < 4; mt++)
            ldsm_x4(a0[mt][0], a0[mt][1], a0[mt][2], a0[mt][3],
                    abase + mt * 16 * STR * 2);
#pragma unroll
        for (int np = 0; np < 2; np++)
            ldsm_x4(b0[2 * np][0], b0[2 * np][1], b0[2 * np + 1][0], b0[2 * np + 1][1],
                    bbase + np * 16 * STR * 2);
#pragma unroll
        for (int np = 0; np < 2; np++)
            ldsm_x4(b1[2 * np][0], b1[2 * np][1], b1[2 * np + 1][0], b1[2 * np + 1][1],
                    bbase + np * 16 * STR * 2 + 32);
        // first half of k0 MMAs
#pragma unroll
        for (int mt = 0; mt < 2; mt++)
#pragma unroll
            for (int nt = 0; nt < 4; nt++)
                mma16816(acc[mt][nt], a0[mt], b0[nt]);
        // A(k1) loads — latency hidden under remaining k0 MMAs
#pragma unroll
        for (int mt = 0; mt < 4; mt++)
            ldsm_x4(a1[mt][0], a1[mt][1], a1[mt][2], a1[mt][3],
                    abase + mt * 16 * STR * 2 + 32);
        // second half of k0 MMAs
#pragma unroll
        for (int mt = 2; mt < 4; mt++)
#pragma unroll
            for (int nt = 0; nt < 4; nt++)
                mma16816(acc[mt][nt], a0[mt], b0[nt]);
        // k1 MMAs
#pragma unroll
        for (int mt = 0; mt < 4; mt++)
#pragma unroll
            for (int nt = 0; nt < 4; nt++)
                mma16816(acc[mt][nt], a1[mt], b1[nt]);
    }

    // ---------------- fused epilogue ----------------
    auto apply = [&](int r, int c, float v0, float v1) {
        if (mode == GT_PRE) {
            v0 += bias[c]; v1 += bias[c + 1];
            if (c < 768) {
                g_F[(size_t)r * 768 + c] = v0;
                g_F[(size_t)r * 768 + c + 1] = v1;
            } else {
                g_P[(size_t)r * 256 + c - 768] = v0;
                g_P[(size_t)r * 256 + c - 767] = v1;
            }
        } else if (mode == GT_KV) {
            dst[(size_t)r * 512 + c] = v0 + bias[c];
            dst[(size_t)r * 512 + c + 1] = v1 + bias[c + 1];
        } else if (mode == GT_ZR) {
            if (c < 256) {
                g_z[(size_t)r * 256 + c] = sigmoidf_(g_F[(size_t)r * 768 + c] + v0);
                g_z[(size_t)r * 256 + c + 1] = sigmoidf_(g_F[(size_t)r * 768 + c + 1] + v1);
            } else {
                int cc = c - 256;
                float rv0 = sigmoidf_(g_F[(size_t)r * 768 + 256 + cc] + v0) *
                            g_sumh[(size_t)r * 256 + cc];
                float rv1 = sigmoidf_(g_F[(size_t)r * 768 + 257 + cc] + v1) *
                            g_sumh[(size_t)r * 256 + cc + 1];
                split_bf16(rv0, g_rs16h[(size_t)r * 256 + cc], g_rs16l[(size_t)r * 256 + cc]);
                split_bf16(rv1, g_rs16h[(size_t)r * 256 + cc + 1], g_rs16l[(size_t)r * 256 + cc + 1]);
            }
        } else {  // GT_FINAL
            float pre0 = tanhf(g_F[(size_t)r * 768 + 512 + c] + v0);
            float pre1 = tanhf(g_F[(size_t)r * 768 + 513 + c] + v1);
            float z0 = g_z[(size_t)r * 256 + c], z1 = g_z[(size_t)r * 256 + c + 1];
            float s0 = g_sumh[(size_t)r * 256 + c], s1 = g_sumh[(size_t)r * 256 + c + 1];
            float nh0 = (1.0f - z0) * s0 + z0 * pre0;
            float nh1 = (1.0f - z1) * s1 + z1 * pre1;
            if (r == 0) { nh0 = 0.0f; nh1 = 0.0f; }
            dst[(size_t)r * 256 + c] = nh0;
            dst[(size_t)r * 256 + c + 1] = nh1;
            split_bf16(nh0, g_h16h[(size_t)r * 256 + c], g_h16l[(size_t)r * 256 + c]);
            split_bf16(nh1, g_h16h[(size_t)r * 256 + c + 1], g_h16l[(size_t)r * 256 + c + 1]);
        }
    };

#pragma unroll
    for (int mt = 0; mt < 4; mt++) {
#pragma unroll
        for (int nt = 0; nt < 4; nt++) {
            int r = row0 + wm + mt * 16 + (lane >> 2);
            int c = col0 + wn + nt * 8 + ((lane & 3) << 1);
            apply(r, c, acc[mt][nt][0], acc[mt][nt][1]);
            apply(r + 8, c, acc[mt][nt][2], acc[mt][nt][3]);
        }
    }
}

// ---------------- qscore ------------------------------------------------------
__global__ void qscore_kernel(const float* __restrict__ alpha) {
    int warp = threadIdx.x >> 5, lane = threadIdx.x & 31;
    int n = blockIdx.x * 8 + warp;
    float acc[4] = {0.f, 0.f, 0.f, 0.f};
#pragma unroll
    for (int tt = 0; tt < 8; tt++) {
        int c = lane + 32 * tt;
        float v = g_P[(size_t)n * H + c];
        float lr = v >= 0.f ? v : 0.01f * v;
        acc[tt >> 1] += lr * alpha[(tt >> 1) * 128 + (c & 63)];
    }
#pragma unroll
    for (int hh = 0; hh < 4; hh++)
        for (int o = 16; o; o >>= 1)
            acc[hh] += __shfl_xor_sync(0xffffffffu, acc[hh], o);
    if (lane == 0) {
#pragma unroll
        for (int hh = 0; hh < 4; hh++) g_qs[n * 4 + hh] = acc[hh];
    }
}

// ---------------- per-step: kscore + rowsum(h) -------------------------------
__global__ void prep_kernel(const float* __restrict__ alpha) {
    int warp = threadIdx.x >> 5, lane = threadIdx.x & 31;
    int n = blockIdx.x * 8 + warp;
    float rs = 0.f;
    float acc[4] = {0.f, 0.f, 0.f, 0.f};
#pragma unroll
    for (int tt = 0; tt < 8; tt++) {
        int c = lane + 32 * tt;
        rs += g_h[(size_t)n * H + c];
        float v = g_KV[(size_t)n * 512 + c];
        float lr = v >= 0.f ? v : 0.01f * v;
        acc[tt >> 1] += lr * alpha[(tt >> 1) * 128 + 64 + (c & 63)];
    }
    for (int o = 16; o; o >>= 1) {
        rs += __shfl_xor_sync(0xffffffffu, rs, o);
#pragma unroll
        for (int hh = 0; hh < 4; hh++)
            acc[hh] += __shfl_xor_sync(0xffffffffu, acc[hh], o);
    }
    if (lane == 0) {
        g_rowsum[n] = rs;
#pragma unroll
        for (int hh = 0; hh < 4; hh++) g_ks[n * 4 + hh] = acc[hh];
    }
}

// ---------------- attention ---------------------------------------------------
__global__ __launch_bounds__(256)
void attn_kernel(const int* __restrict__ bgraph, const float* __restrict__ abias) {
    int n = blockIdx.x;
    int t = threadIdx.x;
    __shared__ int js[NNB];
    __shared__ float sc[NNB][HEADS];
    __shared__ float wgt[NNB][HEADS];
    if (t < NNB) js[t] = bgraph[n * NNB + t];
    __syncthreads();
    if (t < NNB * HEADS) {
        int m = t >> 2, hh = t & 3;
        int j = js[m];
        float s = g_qs[n * 4 + hh] + g_ks[j * 4 + hh] + abias[hh];
        if (g_rowsum[j] == 0.0f) s = NEG_INF;
        sc[m][hh] = s;
    }
    __syncthreads();
    if (t < HEADS) {
        float mx = -INFINITY;
#pragma unroll
        for (int m = 0; m < NNB; m++) mx = fmaxf(mx, sc[m][t]);
        float e[NNB], ssum = 0.f;
#pragma unroll
        for (int m = 0; m < NNB; m++) { e[m] = expf(sc[m][t] - mx); ssum += e[m]; }
        float inv = 1.0f / ssum;
#pragma unroll
        for (int m = 0; m < NNB; m++) wgt[m][t] = e[m] * inv;
    }
    __syncthreads();
    int hh = t >> 6;
    float acc = 0.f;
#pragma unroll
    for (int m = 0; m < NNB; m++)
        acc += wgt[m][hh] * g_KV[(size_t)js[m] * 512 + 256 + t];
    size_t idx = (size_t)n * H + t;
    g_sumh[idx] = acc;
    split_bf16(acc, g_sh16h[idx], g_sh16l[idx]);
}

// ---------------- launch -------------------------------------------------------
static void* symaddr(const void* s) {
    void* p = nullptr;
    cudaGetSymbolAddress(&p, s);
    return p;
}

extern "C" void kernel_launch(void* const* d_in, const int* in_sizes, int n_in,
                              void* d_out, int out_size) {
    const float* fmess = (const float*)d_in[0];
    const int*   bgraph = (const int*)d_in[1];
    const float* Wq = (const float*)d_in[2];
    const float* bq = (const float*)d_in[3];
    const float* Wk = (const float*)d_in[4];
    const float* bk = (const float*)d_in[5];
    const float* Wv = (const float*)d_in[6];
    const float* bv = (const float*)d_in[7];
    const float* alpha = (const float*)d_in[8];
    const float* abias = (const float*)d_in[9];
    const float* Wz = (const float*)d_in[10];
    const float* bz = (const float*)d_in[11];
    const float* Wr = (const float*)d_in[12];
    const float* Ur = (const float*)d_in[13];
    const float* bur = (const float*)d_in[14];
    const float* Wh = (const float*)d_in[15];
    const float* bh = (const float*)d_in[16];
    float* out = (float*)d_out;

    float* p_h    = (float*)symaddr(g_h);
    float* p_KV   = (float*)symaddr(g_KV);
    void*  p_h16h = symaddr(g_h16h);
    void*  p_h16l = symaddr(g_h16l);
    const __nv_bfloat16* a_h16h = (const __nv_bfloat16*)p_h16h;
    const __nv_bfloat16* a_h16l = (const __nv_bfloat16*)p_h16l;
    const __nv_bfloat16* a_sh_h = (const __nv_bfloat16*)symaddr(g_sh16h);
    const __nv_bfloat16* a_sh_l = (const __nv_bfloat16*)symaddr(g_sh16l);
    const __nv_bfloat16* a_rs_h = (const __nv_bfloat16*)symaddr(g_rs16h);
    const __nv_bfloat16* a_rs_l = (const __nv_bfloat16*)symaddr(g_rs16l);
    const __nv_bfloat16* a_f_h  = (const __nv_bfloat16*)symaddr(g_f16h);
    const __nv_bfloat16* a_f_l  = (const __nv_bfloat16*)symaddr(g_f16l);
    const __nv_bfloat16* w_kv_h = (const __nv_bfloat16*)symaddr(g_Wkvh);
    const __nv_bfloat16* w_kv_l = (const __nv_bfloat16*)symaddr(g_Wkvl);
    const __nv_bfloat16* w_zr_h = (const __nv_bfloat16*)symaddr(g_Wzrh);
    const __nv_bfloat16* w_zr_l = (const __nv_bfloat16*)symaddr(g_Wzrl);
    const __nv_bfloat16* w_h2_h = (const __nv_bfloat16*)symaddr(g_Wh2h);
    const __nv_bfloat16* w_h2_l = (const __nv_bfloat16*)symaddr(g_Wh2l);
    const __nv_bfloat16* w_pr_h = (const __nv_bfloat16*)symaddr(g_Wpreh);
    const __nv_bfloat16* w_pr_l = (const __nv_bfloat16*)symaddr(g_Wprel);
    const float* b_kv  = (const float*)symaddr(g_bkv);
    const float* b_pre = (const float*)symaddr(g_bpre);

    cudaFuncSetAttribute(gemm_mma, cudaFuncAttributeMaxDynamicSharedMemorySize, SMEM_DYN);

    cudaMemsetAsync(p_h, 0, (size_t)N_MSG * H * sizeof(float), 0);
    cudaMemsetAsync(p_h16h, 0, (size_t)N_MSG * H * sizeof(__nv_bfloat16), 0);
    cudaMemsetAsync(p_h16l, 0, (size_t)N_MSG * H * sizeof(__nv_bfloat16), 0);

    pad_fmess<<<(N_MSG * KQ + 255) / 256, 256>>>(fmess);
    pack_all<<<(1024 * KQ + 255) / 256, 256>>>(Wq, bq, Wk, bk, Wv, bv, Wz, bz,
                                               Wr, Ur, bur, Wh, bh);

    // PRE: [F(768) | Qpre(256)] = fmess @ Wpre^T + bpre   (K=192, 3-term bf16)
    gemm_mma<<<dim3(8, 128), 256, SMEM_DYN>>>(a_f_h, a_f_l, w_pr_h, w_pr_l,
                                              b_pre, KQ, GT_PRE, nullptr);
    qscore_kernel<<<N_MSG / 8, 256>>>(alpha);

    for (int step = 0; step < DEPTH; step++) {
        gemm_mma<<<dim3(4, 128), 256, SMEM_DYN>>>(a_h16h, a_h16l, w_kv_h, w_kv_l,
                                                  b_kv, H, GT_KV, p_KV);
        prep_kernel<<<N_MSG / 8, 256>>>(alpha);
        attn_kernel<<<N_MSG, 256>>>(bgraph, abias);
        gemm_mma<<<dim3(4, 128), 256, SMEM_DYN>>>(a_sh_h, a_sh_l, w_zr_h, w_zr_l,
                                                  nullptr, H, GT_ZR, nullptr);
        gemm_mma<<<dim3(2, 128), 256, SMEM_DYN>>>(a_rs_h, a_rs_l, w_h2_h, w_h2_l,
                                                  nullptr, H, GT_FINAL,
                                                  step == DEPTH - 1 ? out : p_h);
    }
    (void)in_sizes; (void)n_in; (void)out_size;
}

// round 8
// speedup vs baseline: 1.1454x; 1.1454x over previous
#include <cuda_runtime.h>
#include <cuda_bf16.h>
#include <cstdint>

#define N_MSG 16384
#define NNB 10
#define IN_F 135
#define KQ 192            // padded fmess K (multiple of 32)
#define H 256
#define HEADS 4
#define DEPTH 5
#define NEG_INF -1e18f

// ---------------- fp32 state ------------------------------------------------
__device__ float g_h[N_MSG * H];
__device__ float g_KV[N_MSG * 2 * H];
__device__ float g_sumh[N_MSG * H];
__device__ float g_z[N_MSG * H];
__device__ float g_F[N_MSG * 3 * H];
__device__ float g_P[N_MSG * H];
__device__ float g_qs[N_MSG * HEADS];
__device__ float g_ks[N_MSG * HEADS];
__device__ float g_rowsum[N_MSG];
__device__ float g_tzr[2 * H];           // step-0: bv @ [Wz2|Ur]^T
// ---------------- bf16 hi/lo GEMM operands ----------------------------------
__device__ __align__(16) __nv_bfloat16 g_h16h[N_MSG * H], g_h16l[N_MSG * H];
__device__ __align__(16) __nv_bfloat16 g_sh16h[N_MSG * H], g_sh16l[N_MSG * H];
__device__ __align__(16) __nv_bfloat16 g_rs16h[N_MSG * H], g_rs16l[N_MSG * H];
__device__ __align__(16) __nv_bfloat16 g_f16h[N_MSG * KQ], g_f16l[N_MSG * KQ];
__device__ __align__(16) __nv_bfloat16 g_Wkvh[512 * H], g_Wkvl[512 * H];
__device__ __align__(16) __nv_bfloat16 g_Wzrh[512 * H], g_Wzrl[512 * H];
__device__ __align__(16) __nv_bfloat16 g_Wh2h[H * H], g_Wh2l[H * H];
__device__ __align__(16) __nv_bfloat16 g_Wpreh[1024 * KQ], g_Wprel[1024 * KQ];
__device__ float g_bkv[512];
__device__ float g_bpre[1024];

// ---------------- helpers ----------------------------------------------------
__device__ __forceinline__ void split_bf16(float x, __nv_bfloat16& hi, __nv_bfloat16& lo) {
    hi = __float2bfloat16(x);
    lo = __float2bfloat16(x - __bfloat162float(hi));
}
__device__ __forceinline__ float sigmoidf_(float x) { return 1.0f / (1.0f + expf(-x)); }

__device__ __forceinline__ uint32_t smem_u32(const void* p) {
    uint32_t a;
    asm("{ .reg .u64 t; cvta.to.shared.u64 t, %1; cvt.u32.u64 %0, t; }" : "=r"(a) : "l"(p));
    return a;
}
__device__ __forceinline__ void ldsm_x4(uint32_t& r0, uint32_t& r1, uint32_t& r2,
                                        uint32_t& r3, uint32_t addr) {
    asm volatile("ldmatrix.sync.aligned.m8n8.x4.shared.b16 {%0,%1,%2,%3}, [%4];"
                 : "=r"(r0), "=r"(r1), "=r"(r2), "=r"(r3) : "r"(addr));
}
__device__ __forceinline__ void mma16816(float* d, const uint32_t* a, const uint32_t* b) {
    asm volatile(
        "mma.sync.aligned.m16n8k16.row.col.f32.bf16.bf16.f32 "
        "{%0,%1,%2,%3}, {%4,%5,%6,%7}, {%8,%9}, {%0,%1,%2,%3};"
        : "+f"(d[0]), "+f"(d[1]), "+f"(d[2]), "+f"(d[3])
        : "r"(a[0]), "r"(a[1]), "r"(a[2]), "r"(a[3]), "r"(b[0]), "r"(b[1]));
}
#define CP16(dst, src) \
    asm volatile("cp.async.cg.shared.global [%0], [%1], 16;" :: "r"(dst), "l"(src))
#define CP_COMMIT() asm volatile("cp.async.commit_group;" ::: "memory")
#define CP_WAIT(n)  asm volatile("cp.async.wait_group %0;" :: "n"(n) : "memory")

// ---------------- pad/split fmess -------------------------------------------
__global__ void pad_fmess(const float* __restrict__ fmess) {
    int i = blockIdx.x * blockDim.x + threadIdx.x;
    if (i >= N_MSG * KQ) return;
    int n = i / KQ, c = i % KQ;
    float x = (c < IN_F) ? fmess[n * IN_F + c] : 0.0f;
    split_bf16(x, g_f16h[i], g_f16l[i]);
}

// ---------------- weight packing --------------------------------------------
__global__ void pack_all(const float* __restrict__ Wq, const float* __restrict__ bq,
                         const float* __restrict__ Wk, const float* __restrict__ bk,
                         const float* __restrict__ Wv, const float* __restrict__ bv,
                         const float* __restrict__ Wz, const float* __restrict__ bz,
                         const float* __restrict__ Wr, const float* __restrict__ Ur,
                         const float* __restrict__ bur,
                         const float* __restrict__ Wh, const float* __restrict__ bh) {
    int i = blockIdx.x * blockDim.x + threadIdx.x;
    const int WIDE = IN_F + H;  // 391
    if (i < 512 * H) {
        int n = i / H, k = i % H;
        float kv = (n < H) ? Wk[n * H + k] : Wv[(n - H) * H + k];
        split_bf16(kv, g_Wkvh[i], g_Wkvl[i]);
        float zr = (n < H) ? Wz[n * WIDE + IN_F + k] : Ur[(n - H) * H + k];
        split_bf16(zr, g_Wzrh[i], g_Wzrl[i]);
    }
    if (i < H * H) {
        int n = i / H, k = i % H;
        split_bf16(Wh[n * WIDE + IN_F + k], g_Wh2h[i], g_Wh2l[i]);
    }
    if (i < 1024 * KQ) {
        int n = i / KQ, k = i % KQ;
        float v = 0.0f;
        if (k < IN_F) {
            if (n < 256) v = Wz[n * WIDE + k];
            else if (n < 512) v = Wr[(n - 256) * IN_F + k];
            else if (n < 768) v = Wh[(n - 512) * WIDE + k];
            else v = Wq[(n - 768) * IN_F + k];
        }
        split_bf16(v, g_Wpreh[i], g_Wprel[i]);
    }
    if (i < 512) g_bkv[i] = (i < 256) ? bk[i] : bv[i - 256];
    if (i < 1024) {
        float b = (i < 256) ? bz[i] : (i < 512) ? bur[i - 256]
                : (i < 768) ? bh[i - 512] : bq[i - 768];
        g_bpre[i] = b;
    }
}

// ---------------- step-0 rank-1 kernels --------------------------------------
// t = bv @ [Wz2 | Ur]^T  (fp32, one warp per output)
__global__ void bv_t_kernel(const float* __restrict__ Wz, const float* __restrict__ Ur,
                            const float* __restrict__ bv) {
    const int WIDE = IN_F + H;
    int o = blockIdx.x * 8 + (threadIdx.x >> 5);
    int lane = threadIdx.x & 31;
    float s = 0.f;
#pragma unroll
    for (int t = 0; t < 8; t++) {
        int k = lane + 32 * t;
        float w = (o < 256) ? Wz[o * WIDE + IN_F + k] : Ur[(o - 256) * H + k];
        s += bv[k] * w;
    }
    for (int d = 16; d; d >>= 1) s += __shfl_xor_sync(0xffffffffu, s, d);
    if (lane == 0) g_tzr[o] = s;
}

// step-0 elementwise: sum_h = bv; z = sigmoid(Fz + t1); rs = sigmoid(Fr + t2)*bv
__global__ void zr0_kernel(const float* __restrict__ bv) {
    int i = blockIdx.x * blockDim.x + threadIdx.x;   // over N*H
    int n = i >> 8, c = i & 255;
    float b = bv[c];
    g_sumh[i] = b;
    g_z[i] = sigmoidf_(g_F[(size_t)n * 768 + c] + g_tzr[c]);
    float rv = sigmoidf_(g_F[(size_t)n * 768 + 256 + c] + g_tzr[256 + c]) * b;
    split_bf16(rv, g_rs16h[i], g_rs16l[i]);
}

// ---------------- mma.sync GEMM: 128x128 tile, 3-term split-bf16 -------------
#define GT_PRE 0
#define GT_KV 1
#define GT_ZR 2
#define GT_FINAL 3
#define STR 40                  // padded smem row stride (bf16); conflict-free
#define STAGEB (128 * STR * 2)  // 10240 bytes per stage per operand
#define SMEM_DYN (8 * STAGEB)   // 4 stages x (A + B)

__global__ __launch_bounds__(256, 2)
void gemm_mma(const __nv_bfloat16* __restrict__ Ah, const __nv_bfloat16* __restrict__ Al,
              const __nv_bfloat16* __restrict__ Bh, const __nv_bfloat16* __restrict__ Bl,
              const float* __restrict__ bias, int Kp, int mode, float* __restrict__ dst) {
    extern __shared__ __nv_bfloat16 dsm[];
    const uint32_t sA0 = smem_u32(dsm);
    const uint32_t sB0 = sA0 + 4 * STAGEB;

    const int tid = threadIdx.x, lane = tid & 31, wid = tid >> 5;
    const int wm = (wid & 1) * 64, wn = (wid >> 1) * 32;
    const int row0 = blockIdx.y * 128, col0 = blockIdx.x * 128;

    const int arow = wm + (lane & 15), ak = (lane >> 4) << 3;
    const int g = lane >> 3;
    const int brow = wn + ((g >> 1) << 3) + (lane & 7), bk = (g & 1) << 3;
    const uint32_t aoff_l = (uint32_t)(arow * STR + ak) * 2;
    const uint32_t boff_l = (uint32_t)(brow * STR + bk) * 2;

    const int cpp = Kp >> 5;
    const int NC = 3 * cpp;

    auto seg = [&](int c, const __nv_bfloat16*& Aseg, const __nv_bfloat16*& Bseg, int& kk) {
        int p = c / cpp;
        kk = (c - p * cpp) << 5;
        Aseg = (p < 2) ? Ah : Al;   // [hi, hi, lo]
        Bseg = (p == 1) ? Bl : Bh;  // [hi, lo, hi]
    };
    auto issue = [&](int c) {
        const __nv_bfloat16 *Aseg, *Bseg; int kk;
        seg(c, Aseg, Bseg, kk);
        const uint32_t abase = sA0 + (uint32_t)(c & 3) * STAGEB;
        const uint32_t bbase = sB0 + (uint32_t)(c & 3) * STAGEB;
#pragma unroll
        for (int i = 0; i < 2; i++) {
            int t2 = tid + (i << 8);
            int row = t2 >> 2, coli = (t2 & 3) << 3;
            uint32_t so = (uint32_t)(row * STR + coli) * 2;
            CP16(abase + so, Aseg + (size_t)(row0 + row) * Kp + kk + coli);
            CP16(bbase + so, Bseg + (size_t)(col0 + row) * Kp + kk + coli);
        }
        CP_COMMIT();
    };

    float acc[4][4][4];
#pragma unroll
    for (int i = 0; i < 4; i++)
#pragma unroll
        for (int j = 0; j < 4; j++)
#pragma unroll
            for (int q = 0; q < 4; q++) acc[i][j][q] = 0.f;

    issue(0); issue(1); issue(2);

    for (int c = 0; c < NC; c++) {
        const int allowed = NC - 1 - c;
        if (allowed >= 2)      CP_WAIT(2);
        else if (allowed == 1) CP_WAIT(1);
        else                   CP_WAIT(0);
        __syncthreads();
        if (c + 3 < NC) issue(c + 3);

        const uint32_t abase = sA0 + (uint32_t)(c & 3) * STAGEB + aoff_l;
        const uint32_t bbase = sB0 + (uint32_t)(c & 3) * STAGEB + boff_l;
#pragma unroll
        for (int kk2 = 0; kk2 < 2; kk2++) {
            uint32_t a[4][4], bf[4][2];
#pragma unroll
            for (int mt = 0; mt < 4; mt++)
                ldsm_x4(a[mt][0], a[mt][1], a[mt][2], a[mt][3],
                        abase + mt * 16 * STR * 2 + kk2 * 32);
#pragma unroll
            for (int np = 0; np < 2; np++)
                ldsm_x4(bf[2 * np][0], bf[2 * np][1], bf[2 * np + 1][0], bf[2 * np + 1][1],
                        bbase + np * 16 * STR * 2 + kk2 * 32);
#pragma unroll
            for (int mt = 0; mt < 4; mt++)
#pragma unroll
                for (int nt = 0; nt < 4; nt++)
                    mma16816(acc[mt][nt], a[mt], bf[nt]);
        }
    }

    // ---------------- fused epilogue ----------------
    auto apply = [&](int r, int c, float v0, float v1) {
        if (mode == GT_PRE) {
            v0 += bias[c]; v1 += bias[c + 1];
            if (c < 768) {
                g_F[(size_t)r * 768 + c] = v0;
                g_F[(size_t)r * 768 + c + 1] = v1;
            } else {
                g_P[(size_t)r * 256 + c - 768] = v0;
                g_P[(size_t)r * 256 + c - 767] = v1;
            }
        } else if (mode == GT_KV) {
            dst[(size_t)r * 512 + c] = v0 + bias[c];
            dst[(size_t)r * 512 + c + 1] = v1 + bias[c + 1];
        } else if (mode == GT_ZR) {
            if (c < 256) {
                g_z[(size_t)r * 256 + c] = sigmoidf_(g_F[(size_t)r * 768 + c] + v0);
                g_z[(size_t)r * 256 + c + 1] = sigmoidf_(g_F[(size_t)r * 768 + c + 1] + v1);
            } else {
                int cc = c - 256;
                float rv0 = sigmoidf_(g_F[(size_t)r * 768 + 256 + cc] + v0) *
                            g_sumh[(size_t)r * 256 + cc];
                float rv1 = sigmoidf_(g_F[(size_t)r * 768 + 257 + cc] + v1) *
                            g_sumh[(size_t)r * 256 + cc + 1];
                split_bf16(rv0, g_rs16h[(size_t)r * 256 + cc], g_rs16l[(size_t)r * 256 + cc]);
                split_bf16(rv1, g_rs16h[(size_t)r * 256 + cc + 1], g_rs16l[(size_t)r * 256 + cc + 1]);
            }
        } else {  // GT_FINAL
            float pre0 = tanhf(g_F[(size_t)r * 768 + 512 + c] + v0);
            float pre1 = tanhf(g_F[(size_t)r * 768 + 513 + c] + v1);
            float z0 = g_z[(size_t)r * 256 + c], z1 = g_z[(size_t)r * 256 + c + 1];
            float s0 = g_sumh[(size_t)r * 256 + c], s1 = g_sumh[(size_t)r * 256 + c + 1];
            float nh0 = (1.0f - z0) * s0 + z0 * pre0;
            float nh1 = (1.0f - z1) * s1 + z1 * pre1;
            if (r == 0) { nh0 = 0.0f; nh1 = 0.0f; }
            dst[(size_t)r * 256 + c] = nh0;
            dst[(size_t)r * 256 + c + 1] = nh1;
            split_bf16(nh0, g_h16h[(size_t)r * 256 + c], g_h16l[(size_t)r * 256 + c]);
            split_bf16(nh1, g_h16h[(size_t)r * 256 + c + 1], g_h16l[(size_t)r * 256 + c + 1]);
        }
    };

#pragma unroll
    for (int mt = 0; mt < 4; mt++) {
#pragma unroll
        for (int nt = 0; nt < 4; nt++) {
            int r = row0 + wm + mt * 16 + (lane >> 2);
            int c = col0 + wn + nt * 8 + ((lane & 3) << 1);
            apply(r, c, acc[mt][nt][0], acc[mt][nt][1]);
            apply(r + 8, c, acc[mt][nt][2], acc[mt][nt][3]);
        }
    }
}

// ---------------- qscore ------------------------------------------------------
__global__ void qscore_kernel(const float* __restrict__ alpha) {
    int warp = threadIdx.x >> 5, lane = threadIdx.x & 31;
    int n = blockIdx.x * 8 + warp;
    float acc[4] = {0.f, 0.f, 0.f, 0.f};
#pragma unroll
    for (int tt = 0; tt < 8; tt++) {
        int c = lane + 32 * tt;
        float v = g_P[(size_t)n * H + c];
        float lr = v >= 0.f ? v : 0.01f * v;
        acc[tt >> 1] += lr * alpha[(tt >> 1) * 128 + (c & 63)];
    }
#pragma unroll
    for (int hh = 0; hh < 4; hh++)
        for (int o = 16; o; o >>= 1)
            acc[hh] += __shfl_xor_sync(0xffffffffu, acc[hh], o);
    if (lane == 0) {
#pragma unroll
        for (int hh = 0; hh < 4; hh++) g_qs[n * 4 + hh] = acc[hh];
    }
}

// ---------------- per-step: kscore + rowsum(h) -------------------------------
__global__ void prep_kernel(const float* __restrict__ alpha) {
    int warp = threadIdx.x >> 5, lane = threadIdx.x & 31;
    int n = blockIdx.x * 8 + warp;
    float rs = 0.f;
    float acc[4] = {0.f, 0.f, 0.f, 0.f};
#pragma unroll
    for (int tt = 0; tt < 8; tt++) {
        int c = lane + 32 * tt;
        rs += g_h[(size_t)n * H + c];
        float v = g_KV[(size_t)n * 512 + c];
        float lr = v >= 0.f ? v : 0.01f * v;
        acc[tt >> 1] += lr * alpha[(tt >> 1) * 128 + 64 + (c & 63)];
    }
    for (int o = 16; o; o >>= 1) {
        rs += __shfl_xor_sync(0xffffffffu, rs, o);
#pragma unroll
        for (int hh = 0; hh < 4; hh++)
            acc[hh] += __shfl_xor_sync(0xffffffffu, acc[hh], o);
    }
    if (lane == 0) {
        g_rowsum[n] = rs;
#pragma unroll
        for (int hh = 0; hh < 4; hh++) g_ks[n * 4 + hh] = acc[hh];
    }
}

// ---------------- attention ---------------------------------------------------
__global__ __launch_bounds__(256)
void attn_kernel(const int* __restrict__ bgraph, const float* __restrict__ abias) {
    int n = blockIdx.x;
    int t = threadIdx.x;
    __shared__ int js[NNB];
    __shared__ float sc[NNB][HEADS];
    __shared__ float wgt[NNB][HEADS];
    if (t < NNB) js[t] = bgraph[n * NNB + t];
    __syncthreads();
    if (t < NNB * HEADS) {
        int m = t >> 2, hh = t & 3;
        int j = js[m];
        float s = g_qs[n * 4 + hh] + g_ks[j * 4 + hh] + abias[hh];
        if (g_rowsum[j] == 0.0f) s = NEG_INF;
        sc[m][hh] = s;
    }
    __syncthreads();
    if (t < HEADS) {
        float mx = -INFINITY;
#pragma unroll
        for (int m = 0; m < NNB; m++) mx = fmaxf(mx, sc[m][t]);
        float e[NNB], ssum = 0.f;
#pragma unroll
        for (int m = 0; m < NNB; m++) { e[m] = expf(sc[m][t] - mx); ssum += e[m]; }
        float inv = 1.0f / ssum;
#pragma unroll
        for (int m = 0; m < NNB; m++) wgt[m][t] = e[m] * inv;
    }
    __syncthreads();
    int hh = t >> 6;
    float acc = 0.f;
#pragma unroll
    for (int m = 0; m < NNB; m++)
        acc += wgt[m][hh] * g_KV[(size_t)js[m] * 512 + 256 + t];
    size_t idx = (size_t)n * H + t;
    g_sumh[idx] = acc;
    split_bf16(acc, g_sh16h[idx], g_sh16l[idx]);
}

// ---------------- launch -------------------------------------------------------
static void* symaddr(const void* s) {
    void* p = nullptr;
    cudaGetSymbolAddress(&p, s);
    return p;
}

extern "C" void kernel_launch(void* const* d_in, const int* in_sizes, int n_in,
                              void* d_out, int out_size) {
    const float* fmess = (const float*)d_in[0];
    const int*   bgraph = (const int*)d_in[1];
    const float* Wq = (const float*)d_in[2];
    const float* bq = (const float*)d_in[3];
    const float* Wk = (const float*)d_in[4];
    const float* bk = (const float*)d_in[5];
    const float* Wv = (const float*)d_in[6];
    const float* bv = (const float*)d_in[7];
    const float* alpha = (const float*)d_in[8];
    const float* abias = (const float*)d_in[9];
    const float* Wz = (const float*)d_in[10];
    const float* bz = (const float*)d_in[11];
    const float* Wr = (const float*)d_in[12];
    const float* Ur = (const float*)d_in[13];
    const float* bur = (const float*)d_in[14];
    const float* Wh = (const float*)d_in[15];
    const float* bh = (const float*)d_in[16];
    float* out = (float*)d_out;

    float* p_h  = (float*)symaddr(g_h);
    float* p_KV = (float*)symaddr(g_KV);
    const __nv_bfloat16* a_h16h = (const __nv_bfloat16*)symaddr(g_h16h);
    const __nv_bfloat16* a_h16l = (const __nv_bfloat16*)symaddr(g_h16l);
    const __nv_bfloat16* a_sh_h = (const __nv_bfloat16*)symaddr(g_sh16h);
    const __nv_bfloat16* a_sh_l = (const __nv_bfloat16*)symaddr(g_sh16l);
    const __nv_bfloat16* a_rs_h = (const __nv_bfloat16*)symaddr(g_rs16h);
    const __nv_bfloat16* a_rs_l = (const __nv_bfloat16*)symaddr(g_rs16l);
    const __nv_bfloat16* a_f_h  = (const __nv_bfloat16*)symaddr(g_f16h);
    const __nv_bfloat16* a_f_l  = (const __nv_bfloat16*)symaddr(g_f16l);
    const __nv_bfloat16* w_kv_h = (const __nv_bfloat16*)symaddr(g_Wkvh);
    const __nv_bfloat16* w_kv_l = (const __nv_bfloat16*)symaddr(g_Wkvl);
    const __nv_bfloat16* w_zr_h = (const __nv_bfloat16*)symaddr(g_Wzrh);
    const __nv_bfloat16* w_zr_l = (const __nv_bfloat16*)symaddr(g_Wzrl);
    const __nv_bfloat16* w_h2_h = (const __nv_bfloat16*)symaddr(g_Wh2h);
    const __nv_bfloat16* w_h2_l = (const __nv_bfloat16*)symaddr(g_Wh2l);
    const __nv_bfloat16* w_pr_h = (const __nv_bfloat16*)symaddr(g_Wpreh);
    const __nv_bfloat16* w_pr_l = (const __nv_bfloat16*)symaddr(g_Wprel);
    const float* b_kv  = (const float*)symaddr(g_bkv);
    const float* b_pre = (const float*)symaddr(g_bpre);

    cudaFuncSetAttribute(gemm_mma, cudaFuncAttributeMaxDynamicSharedMemorySize, SMEM_DYN);

    pad_fmess<<<(N_MSG * KQ + 255) / 256, 256>>>(fmess);
    pack_all<<<(1024 * KQ + 255) / 256, 256>>>(Wq, bq, Wk, bk, Wv, bv, Wz, bz,
                                               Wr, Ur, bur, Wh, bh);

    // PRE: [F(768) | Qpre(256)] = fmess @ Wpre^T + bpre   (K=192, 3-term bf16)
    gemm_mma<<<dim3(8, 128), 256, SMEM_DYN>>>(a_f_h, a_f_l, w_pr_h, w_pr_l,
                                              b_pre, KQ, GT_PRE, nullptr);
    qscore_kernel<<<N_MSG / 8, 256>>>(alpha);

    // ---- step 0 (exact rank-1 shortcut: h=0 => sum_h = bv for every row) ----
    bv_t_kernel<<<64, 256>>>(Wz, Ur, bv);
    zr0_kernel<<<N_MSG * H / 256, 256>>>(bv);
    gemm_mma<<<dim3(2, 128), 256, SMEM_DYN>>>(a_rs_h, a_rs_l, w_h2_h, w_h2_l,
                                              nullptr, H, GT_FINAL, p_h);

    // ---- steps 1..DEPTH-1 ----
    for (int step = 1; step < DEPTH; step++) {
        gemm_mma<<<dim3(4, 128), 256, SMEM_DYN>>>(a_h16h, a_h16l, w_kv_h, w_kv_l,
                                                  b_kv, H, GT_KV, p_KV);
        prep_kernel<<<N_MSG / 8, 256>>>(alpha);
        attn_kernel<<<N_MSG, 256>>>(bgraph, abias);
        gemm_mma<<<dim3(4, 128), 256, SMEM_DYN>>>(a_sh_h, a_sh_l, w_zr_h, w_zr_l,
                                                  nullptr, H, GT_ZR, nullptr);
        gemm_mma<<<dim3(2, 128), 256, SMEM_DYN>>>(a_rs_h, a_rs_l, w_h2_h, w_h2_l,
                                                  nullptr, H, GT_FINAL,
                                                  step == DEPTH - 1 ? out : p_h);
    }
    (void)in_sizes; (void)n_in; (void)out_size;
}

// round 9
// speedup vs baseline: 1.3570x; 1.1848x over previous
#include <cuda_runtime.h>
#include <cuda_fp16.h>
#include <cstdint>

#define N_MSG 16384
#define NNB 10
#define IN_F 135
#define KQ 192            // padded fmess K (multiple of 32)
#define H 256
#define HEADS 4
#define DEPTH 5
#define NEG_INF -1e18f

// ---------------- fp32 state ------------------------------------------------
__device__ float g_h[N_MSG * H];
__device__ float g_KV[N_MSG * 2 * H];
__device__ float g_sumh[N_MSG * H];
__device__ float g_z[N_MSG * H];
__device__ float g_F[N_MSG * 3 * H];
__device__ float g_P[N_MSG * H];
__device__ float g_qs[N_MSG * HEADS];
__device__ float g_ks[N_MSG * HEADS];
__device__ float g_rowsum[N_MSG];
__device__ float g_tzr[2 * H];           // step-0: bv @ [Wz2|Ur]^T
// ---------------- fp16 GEMM operands ----------------------------------------
// Activations (A side): exact via hi+lo. Weights (B side): single fp16.
__device__ __align__(16) __half g_h16h[N_MSG * H], g_h16l[N_MSG * H];
__device__ __align__(16) __half g_sh16h[N_MSG * H], g_sh16l[N_MSG * H];
__device__ __align__(16) __half g_rs16h[N_MSG * H], g_rs16l[N_MSG * H];
__device__ __align__(16) __half g_f16h[N_MSG * KQ], g_f16l[N_MSG * KQ];
__device__ __align__(16) __half g_Wkv16[512 * H];
__device__ __align__(16) __half g_Wzr16[512 * H];
__device__ __align__(16) __half g_Wh216[H * H];
__device__ __align__(16) __half g_Wpre16[1024 * KQ];
__device__ float g_bkv[512];
__device__ float g_bpre[1024];

// ---------------- helpers ----------------------------------------------------
__device__ __forceinline__ void split_f16(float x, __half& hi, __half& lo) {
    hi = __float2half_rn(x);
    lo = __float2half_rn(x - __half2float(hi));
}
__device__ __forceinline__ float sigmoidf_(float x) { return 1.0f / (1.0f + expf(-x)); }

__device__ __forceinline__ uint32_t smem_u32(const void* p) {
    uint32_t a;
    asm("{ .reg .u64 t; cvta.to.shared.u64 t, %1; cvt.u32.u64 %0, t; }" : "=r"(a) : "l"(p));
    return a;
}
__device__ __forceinline__ void ldsm_x4(uint32_t& r0, uint32_t& r1, uint32_t& r2,
                                        uint32_t& r3, uint32_t addr) {
    asm volatile("ldmatrix.sync.aligned.m8n8.x4.shared.b16 {%0,%1,%2,%3}, [%4];"
                 : "=r"(r0), "=r"(r1), "=r"(r2), "=r"(r3) : "r"(addr));
}
__device__ __forceinline__ void mma16816(float* d, const uint32_t* a, const uint32_t* b) {
    asm volatile(
        "mma.sync.aligned.m16n8k16.row.col.f32.f16.f16.f32 "
        "{%0,%1,%2,%3}, {%4,%5,%6,%7}, {%8,%9}, {%0,%1,%2,%3};"
        : "+f"(d[0]), "+f"(d[1]), "+f"(d[2]), "+f"(d[3])
        : "r"(a[0]), "r"(a[1]), "r"(a[2]), "r"(a[3]), "r"(b[0]), "r"(b[1]));
}
#define CP16(dst, src) \
    asm volatile("cp.async.cg.shared.global [%0], [%1], 16;" :: "r"(dst), "l"(src))
#define CP_COMMIT() asm volatile("cp.async.commit_group;" ::: "memory")
#define CP_WAIT(n)  asm volatile("cp.async.wait_group %0;" :: "n"(n) : "memory")

// ---------------- pad/split fmess -------------------------------------------
__global__ void pad_fmess(const float* __restrict__ fmess) {
    int i = blockIdx.x * blockDim.x + threadIdx.x;
    if (i >= N_MSG * KQ) return;
    int n = i / KQ, c = i % KQ;
    float x = (c < IN_F) ? fmess[n * IN_F + c] : 0.0f;
    split_f16(x, g_f16h[i], g_f16l[i]);
}

// ---------------- weight packing --------------------------------------------
__global__ void pack_all(const float* __restrict__ Wq, const float* __restrict__ bq,
                         const float* __restrict__ Wk, const float* __restrict__ bk,
                         const float* __restrict__ Wv, const float* __restrict__ bv,
                         const float* __restrict__ Wz, const float* __restrict__ bz,
                         const float* __restrict__ Wr, const float* __restrict__ Ur,
                         const float* __restrict__ bur,
                         const float* __restrict__ Wh, const float* __restrict__ bh) {
    int i = blockIdx.x * blockDim.x + threadIdx.x;
    const int WIDE = IN_F + H;  // 391
    if (i < 512 * H) {
        int n = i / H, k = i % H;
        float kv = (n < H) ? Wk[n * H + k] : Wv[(n - H) * H + k];
        g_Wkv16[i] = __float2half_rn(kv);
        float zr = (n < H) ? Wz[n * WIDE + IN_F + k] : Ur[(n - H) * H + k];
        g_Wzr16[i] = __float2half_rn(zr);
    }
    if (i < H * H) {
        int n = i / H, k = i % H;
        g_Wh216[i] = __float2half_rn(Wh[n * WIDE + IN_F + k]);
    }
    if (i < 1024 * KQ) {
        int n = i / KQ, k = i % KQ;
        float v = 0.0f;
        if (k < IN_F) {
            if (n < 256) v = Wz[n * WIDE + k];
            else if (n < 512) v = Wr[(n - 256) * IN_F + k];
            else if (n < 768) v = Wh[(n - 512) * WIDE + k];
            else v = Wq[(n - 768) * IN_F + k];
        }
        g_Wpre16[i] = __float2half_rn(v);
    }
    if (i < 512) g_bkv[i] = (i < 256) ? bk[i] : bv[i - 256];
    if (i < 1024) {
        float b = (i < 256) ? bz[i] : (i < 512) ? bur[i - 256]
                : (i < 768) ? bh[i - 512] : bq[i - 768];
        g_bpre[i] = b;
    }
}

// ---------------- step-0 rank-1 kernels --------------------------------------
__global__ void bv_t_kernel(const float* __restrict__ Wz, const float* __restrict__ Ur,
                            const float* __restrict__ bv) {
    const int WIDE = IN_F + H;
    int o = blockIdx.x * 8 + (threadIdx.x >> 5);
    int lane = threadIdx.x & 31;
    float s = 0.f;
#pragma unroll
    for (int t = 0; t < 8; t++) {
        int k = lane + 32 * t;
        float w = (o < 256) ? Wz[o * WIDE + IN_F + k] : Ur[(o - 256) * H + k];
        s += bv[k] * w;
    }
    for (int d = 16; d; d >>= 1) s += __shfl_xor_sync(0xffffffffu, s, d);
    if (lane == 0) g_tzr[o] = s;
}

__global__ void zr0_kernel(const float* __restrict__ bv) {
    int i = blockIdx.x * blockDim.x + threadIdx.x;   // over N*H
    int n = i >> 8, c = i & 255;
    float b = bv[c];
    g_sumh[i] = b;
    g_z[i] = sigmoidf_(g_F[(size_t)n * 768 + c] + g_tzr[c]);
    float rv = sigmoidf_(g_F[(size_t)n * 768 + 256 + c] + g_tzr[256 + c]) * b;
    split_f16(rv, g_rs16h[i], g_rs16l[i]);
}

// ---------------- mma.sync GEMM: 128x128 tile, 2-term fp16 split -------------
// C = (A_hi + A_lo) * B_fp16; two K-phases [A_hi, A_lo] against same B.
#define GT_PRE 0
#define GT_KV 1
#define GT_ZR 2
#define GT_FINAL 3
#define STR 40                  // padded smem row stride (fp16); conflict-free
#define STAGEB (128 * STR * 2)  // 10240 bytes per stage per operand
#define SMEM_DYN (8 * STAGEB)   // 4 stages x (A + B)

__global__ __launch_bounds__(256, 2)
void gemm_mma(const __half* __restrict__ Ah, const __half* __restrict__ Al,
              const __half* __restrict__ Bw,
              const float* __restrict__ bias, int Kp, int mode, float* __restrict__ dst) {
    extern __shared__ __half dsm[];
    const uint32_t sA0 = smem_u32(dsm);
    const uint32_t sB0 = sA0 + 4 * STAGEB;

    const int tid = threadIdx.x, lane = tid & 31, wid = tid >> 5;
    const int wm = (wid & 1) * 64, wn = (wid >> 1) * 32;
    const int row0 = blockIdx.y * 128, col0 = blockIdx.x * 128;

    const int arow = wm + (lane & 15), ak = (lane >> 4) << 3;
    const int g = lane >> 3;
    const int brow = wn + ((g >> 1) << 3) + (lane & 7), bk = (g & 1) << 3;
    const uint32_t aoff_l = (uint32_t)(arow * STR + ak) * 2;
    const uint32_t boff_l = (uint32_t)(brow * STR + bk) * 2;

    const int cpp = Kp >> 5;
    const int NC = 2 * cpp;     // 2 phases: A_hi, A_lo

    auto seg = [&](int c, const __half*& Aseg, int& kk) {
        int p = c / cpp;
        kk = (c - p * cpp) << 5;
        Aseg = (p == 0) ? Ah : Al;
    };
    auto issue = [&](int c) {
        const __half* Aseg; int kk;
        seg(c, Aseg, kk);
        const uint32_t abase = sA0 + (uint32_t)(c & 3) * STAGEB;
        const uint32_t bbase = sB0 + (uint32_t)(c & 3) * STAGEB;
#pragma unroll
        for (int i = 0; i < 2; i++) {
            int t2 = tid + (i << 8);
            int row = t2 >> 2, coli = (t2 & 3) << 3;
            uint32_t so = (uint32_t)(row * STR + coli) * 2;
            CP16(abase + so, Aseg + (size_t)(row0 + row) * Kp + kk + coli);
            CP16(bbase + so, Bw + (size_t)(col0 + row) * Kp + kk + coli);
        }
        CP_COMMIT();
    };

    float acc[4][4][4];
#pragma unroll
    for (int i = 0; i < 4; i++)
#pragma unroll
        for (int j = 0; j < 4; j++)
#pragma unroll
            for (int q = 0; q < 4; q++) acc[i][j][q] = 0.f;

    issue(0); issue(1); issue(2);

    for (int c = 0; c < NC; c++) {
        const int allowed = NC - 1 - c;
        if (allowed >= 2)      CP_WAIT(2);
        else if (allowed == 1) CP_WAIT(1);
        else                   CP_WAIT(0);
        __syncthreads();
        if (c + 3 < NC) issue(c + 3);

        const uint32_t abase = sA0 + (uint32_t)(c & 3) * STAGEB + aoff_l;
        const uint32_t bbase = sB0 + (uint32_t)(c & 3) * STAGEB + boff_l;
#pragma unroll
        for (int kk2 = 0; kk2 < 2; kk2++) {
            uint32_t a[4][4], bf[4][2];
#pragma unroll
            for (int mt = 0; mt < 4; mt++)
                ldsm_x4(a[mt][0], a[mt][1], a[mt][2], a[mt][3],
                        abase + mt * 16 * STR * 2 + kk2 * 32);
#pragma unroll
            for (int np = 0; np < 2; np++)
                ldsm_x4(bf[2 * np][0], bf[2 * np][1], bf[2 * np + 1][0], bf[2 * np + 1][1],
                        bbase + np * 16 * STR * 2 + kk2 * 32);
#pragma unroll
            for (int mt = 0; mt < 4; mt++)
#pragma unroll
                for (int nt = 0; nt < 4; nt++)
                    mma16816(acc[mt][nt], a[mt], bf[nt]);
        }
    }

    // ---------------- fused epilogue ----------------
    auto apply = [&](int r, int c, float v0, float v1) {
        if (mode == GT_PRE) {
            v0 += bias[c]; v1 += bias[c + 1];
            if (c < 768) {
                g_F[(size_t)r * 768 + c] = v0;
                g_F[(size_t)r * 768 + c + 1] = v1;
            } else {
                g_P[(size_t)r * 256 + c - 768] = v0;
                g_P[(size_t)r * 256 + c - 767] = v1;
            }
        } else if (mode == GT_KV) {
            dst[(size_t)r * 512 + c] = v0 + bias[c];
            dst[(size_t)r * 512 + c + 1] = v1 + bias[c + 1];
        } else if (mode == GT_ZR) {
            if (c < 256) {
                g_z[(size_t)r * 256 + c] = sigmoidf_(g_F[(size_t)r * 768 + c] + v0);
                g_z[(size_t)r * 256 + c + 1] = sigmoidf_(g_F[(size_t)r * 768 + c + 1] + v1);
            } else {
                int cc = c - 256;
                float rv0 = sigmoidf_(g_F[(size_t)r * 768 + 256 + cc] + v0) *
                            g_sumh[(size_t)r * 256 + cc];
                float rv1 = sigmoidf_(g_F[(size_t)r * 768 + 257 + cc] + v1) *
                            g_sumh[(size_t)r * 256 + cc + 1];
                split_f16(rv0, g_rs16h[(size_t)r * 256 + cc], g_rs16l[(size_t)r * 256 + cc]);
                split_f16(rv1, g_rs16h[(size_t)r * 256 + cc + 1], g_rs16l[(size_t)r * 256 + cc + 1]);
            }
        } else {  // GT_FINAL
            float pre0 = tanhf(g_F[(size_t)r * 768 + 512 + c] + v0);
            float pre1 = tanhf(g_F[(size_t)r * 768 + 513 + c] + v1);
            float z0 = g_z[(size_t)r * 256 + c], z1 = g_z[(size_t)r * 256 + c + 1];
            float s0 = g_sumh[(size_t)r * 256 + c], s1 = g_sumh[(size_t)r * 256 + c + 1];
            float nh0 = (1.0f - z0) * s0 + z0 * pre0;
            float nh1 = (1.0f - z1) * s1 + z1 * pre1;
            if (r == 0) { nh0 = 0.0f; nh1 = 0.0f; }
            dst[(size_t)r * 256 + c] = nh0;
            dst[(size_t)r * 256 + c + 1] = nh1;
            split_f16(nh0, g_h16h[(size_t)r * 256 + c], g_h16l[(size_t)r * 256 + c]);
            split_f16(nh1, g_h16h[(size_t)r * 256 + c + 1], g_h16l[(size_t)r * 256 + c + 1]);
        }
    };

#pragma unroll
    for (int mt = 0; mt < 4; mt++) {
#pragma unroll
        for (int nt = 0; nt < 4; nt++) {
            int r = row0 + wm + mt * 16 + (lane >> 2);
            int c = col0 + wn + nt * 8 + ((lane & 3) << 1);
            apply(r, c, acc[mt][nt][0], acc[mt][nt][1]);
            apply(r + 8, c, acc[mt][nt][2], acc[mt][nt][3]);
        }
    }
}

// ---------------- qscore ------------------------------------------------------
__global__ void qscore_kernel(const float* __restrict__ alpha) {
    int warp = threadIdx.x >> 5, lane = threadIdx.x & 31;
    int n = blockIdx.x * 8 + warp;
    float acc[4] = {0.f, 0.f, 0.f, 0.f};
#pragma unroll
    for (int tt = 0; tt < 8; tt++) {
        int c = lane + 32 * tt;
        float v = g_P[(size_t)n * H + c];
        float lr = v >= 0.f ? v : 0.01f * v;
        acc[tt >> 1] += lr * alpha[(tt >> 1) * 128 + (c & 63)];
    }
#pragma unroll
    for (int hh = 0; hh < 4; hh++)
        for (int o = 16; o; o >>= 1)
            acc[hh] += __shfl_xor_sync(0xffffffffu, acc[hh], o);
    if (lane == 0) {
#pragma unroll
        for (int hh = 0; hh < 4; hh++) g_qs[n * 4 + hh] = acc[hh];
    }
}

// ---------------- per-step: kscore + rowsum(h) -------------------------------
__global__ void prep_kernel(const float* __restrict__ alpha) {
    int warp = threadIdx.x >> 5, lane = threadIdx.x & 31;
    int n = blockIdx.x * 8 + warp;
    float rs = 0.f;
    float acc[4] = {0.f, 0.f, 0.f, 0.f};
#pragma unroll
    for (int tt = 0; tt < 8; tt++) {
        int c = lane + 32 * tt;
        rs += g_h[(size_t)n * H + c];
        float v = g_KV[(size_t)n * 512 + c];
        float lr = v >= 0.f ? v : 0.01f * v;
        acc[tt >> 1] += lr * alpha[(tt >> 1) * 128 + 64 + (c & 63)];
    }
    for (int o = 16; o; o >>= 1) {
        rs += __shfl_xor_sync(0xffffffffu, rs, o);
#pragma unroll
        for (int hh = 0; hh < 4; hh++)
            acc[hh] += __shfl_xor_sync(0xffffffffu, acc[hh], o);
    }
    if (lane == 0) {
        g_rowsum[n] = rs;
#pragma unroll
        for (int hh = 0; hh < 4; hh++) g_ks[n * 4 + hh] = acc[hh];
    }
}

// ---------------- attention ---------------------------------------------------
__global__ __launch_bounds__(256)
void attn_kernel(const int* __restrict__ bgraph, const float* __restrict__ abias) {
    int n = blockIdx.x;
    int t = threadIdx.x;
    __shared__ int js[NNB];
    __shared__ float sc[NNB][HEADS];
    __shared__ float wgt[NNB][HEADS];
    if (t < NNB) js[t] = bgraph[n * NNB + t];
    __syncthreads();
    if (t < NNB * HEADS) {
        int m = t >> 2, hh = t & 3;
        int j = js[m];
        float s = g_qs[n * 4 + hh] + g_ks[j * 4 + hh] + abias[hh];
        if (g_rowsum[j] == 0.0f) s = NEG_INF;
        sc[m][hh] = s;
    }
    __syncthreads();
    if (t < HEADS) {
        float mx = -INFINITY;
#pragma unroll
        for (int m = 0; m < NNB; m++) mx = fmaxf(mx, sc[m][t]);
        float e[NNB], ssum = 0.f;
#pragma unroll
        for (int m = 0; m < NNB; m++) { e[m] = expf(sc[m][t] - mx); ssum += e[m]; }
        float inv = 1.0f / ssum;
#pragma unroll
        for (int m = 0; m < NNB; m++) wgt[m][t] = e[m] * inv;
    }
    __syncthreads();
    int hh = t >> 6;
    float acc = 0.f;
#pragma unroll
    for (int m = 0; m < NNB; m++)
        acc += wgt[m][hh] * g_KV[(size_t)js[m] * 512 + 256 + t];
    size_t idx = (size_t)n * H + t;
    g_sumh[idx] = acc;
    split_f16(acc, g_sh16h[idx], g_sh16l[idx]);
}

// ---------------- launch -------------------------------------------------------
static void* symaddr(const void* s) {
    void* p = nullptr;
    cudaGetSymbolAddress(&p, s);
    return p;
}

extern "C" void kernel_launch(void* const* d_in, const int* in_sizes, int n_in,
                              void* d_out, int out_size) {
    const float* fmess = (const float*)d_in[0];
    const int*   bgraph = (const int*)d_in[1];
    const float* Wq = (const float*)d_in[2];
    const float* bq = (const float*)d_in[3];
    const float* Wk = (const float*)d_in[4];
    const float* bk = (const float*)d_in[5];
    const float* Wv = (const float*)d_in[6];
    const float* bv = (const float*)d_in[7];
    const float* alpha = (const float*)d_in[8];
    const float* abias = (const float*)d_in[9];
    const float* Wz = (const float*)d_in[10];
    const float* bz = (const float*)d_in[11];
    const float* Wr = (const float*)d_in[12];
    const float* Ur = (const float*)d_in[13];
    const float* bur = (const float*)d_in[14];
    const float* Wh = (const float*)d_in[15];
    const float* bh = (const float*)d_in[16];
    float* out = (float*)d_out;

    float* p_h  = (float*)symaddr(g_h);
    float* p_KV = (float*)symaddr(g_KV);
    const __half* a_h16h = (const __half*)symaddr(g_h16h);
    const __half* a_h16l = (const __half*)symaddr(g_h16l);
    const __half* a_sh_h = (const __half*)symaddr(g_sh16h);
    const __half* a_sh_l = (const __half*)symaddr(g_sh16l);
    const __half* a_rs_h = (const __half*)symaddr(g_rs16h);
    const __half* a_rs_l = (const __half*)symaddr(g_rs16l);
    const __half* a_f_h  = (const __half*)symaddr(g_f16h);
    const __half* a_f_l  = (const __half*)symaddr(g_f16l);
    const __half* w_kv   = (const __half*)symaddr(g_Wkv16);
    const __half* w_zr   = (const __half*)symaddr(g_Wzr16);
    const __half* w_h2   = (const __half*)symaddr(g_Wh216);
    const __half* w_pr   = (const __half*)symaddr(g_Wpre16);
    const float* b_kv  = (const float*)symaddr(g_bkv);
    const float* b_pre = (const float*)symaddr(g_bpre);

    cudaFuncSetAttribute(gemm_mma, cudaFuncAttributeMaxDynamicSharedMemorySize, SMEM_DYN);

    pad_fmess<<<(N_MSG * KQ + 255) / 256, 256>>>(fmess);
    pack_all<<<(1024 * KQ + 255) / 256, 256>>>(Wq, bq, Wk, bk, Wv, bv, Wz, bz,
                                               Wr, Ur, bur, Wh, bh);

    // PRE: [F(768) | Qpre(256)] = fmess @ Wpre^T + bpre
    gemm_mma<<<dim3(8, 128), 256, SMEM_DYN>>>(a_f_h, a_f_l, w_pr,
                                              b_pre, KQ, GT_PRE, nullptr);
    qscore_kernel<<<N_MSG / 8, 256>>>(alpha);

    // ---- step 0 (exact rank-1 shortcut: h=0 => sum_h = bv for every row) ----
    bv_t_kernel<<<64, 256>>>(Wz, Ur, bv);
    zr0_kernel<<<N_MSG * H / 256, 256>>>(bv);
    gemm_mma<<<dim3(2, 128), 256, SMEM_DYN>>>(a_rs_h, a_rs_l, w_h2,
                                              nullptr, H, GT_FINAL, p_h);

    // ---- steps 1..DEPTH-1 ----
    for (int step = 1; step < DEPTH; step++) {
        gemm_mma<<<dim3(4, 128), 256, SMEM_DYN>>>(a_h16h, a_h16l, w_kv,
                                                  b_kv, H, GT_KV, p_KV);
        prep_kernel<<<N_MSG / 8, 256>>>(alpha);
        attn_kernel<<<N_MSG, 256>>>(bgraph, abias);
        gemm_mma<<<dim3(4, 128), 256, SMEM_DYN>>>(a_sh_h, a_sh_l, w_zr,
                                                  nullptr, H, GT_ZR, nullptr);
        gemm_mma<<<dim3(2, 128), 256, SMEM_DYN>>>(a_rs_h, a_rs_l, w_h2,
                                                  nullptr, H, GT_FINAL,
                                                  step == DEPTH - 1 ? out : p_h);
    }
    (void)in_sizes; (void)n_in; (void)out_size;
}

// round 10
// speedup vs baseline: 1.7539x; 1.2925x over previous
#include <cuda_runtime.h>
#include <cuda_fp16.h>
#include <cstdint>

#define N_MSG 16384
#define NNB 10
#define IN_F 135
#define KQ 192            // padded fmess K (multiple of 32)
#define H 256
#define HEADS 4
#define DEPTH 5
#define NEG_INF -1e18f

// ---------------- fp32 state ------------------------------------------------
__device__ float g_h[N_MSG * H];
__device__ float g_KV[N_MSG * 2 * H];
__device__ float g_sumh[N_MSG * H];
__device__ float g_z[N_MSG * H];
__device__ float g_F[N_MSG * 3 * H];
__device__ float g_P[N_MSG * H];
__device__ float g_qs[N_MSG * HEADS];
__device__ float g_ks[N_MSG * HEADS];
__device__ float g_rowsum[N_MSG];
__device__ float g_tzr[2 * H];           // step-0: bv @ [Wz2|Ur]^T
// ---------------- fp16 GEMM operands (single-pass) ---------------------------
__device__ __align__(16) __half g_h16[N_MSG * H];
__device__ __align__(16) __half g_sh16[N_MSG * H];
__device__ __align__(16) __half g_rs16[N_MSG * H];
__device__ __align__(16) __half g_f16[N_MSG * KQ];
__device__ __align__(16) __half g_Wkv16[512 * H];
__device__ __align__(16) __half g_Wzr16[512 * H];
__device__ __align__(16) __half g_Wh216[H * H];
__device__ __align__(16) __half g_Wpre16[1024 * KQ];
__device__ float g_bkv[512];
__device__ float g_bpre[1024];

// ---------------- helpers ----------------------------------------------------
__device__ __forceinline__ float sigmoidf_(float x) { return 1.0f / (1.0f + expf(-x)); }

__device__ __forceinline__ uint32_t smem_u32(const void* p) {
    uint32_t a;
    asm("{ .reg .u64 t; cvta.to.shared.u64 t, %1; cvt.u32.u64 %0, t; }" : "=r"(a) : "l"(p));
    return a;
}
__device__ __forceinline__ void ldsm_x4(uint32_t& r0, uint32_t& r1, uint32_t& r2,
                                        uint32_t& r3, uint32_t addr) {
    asm volatile("ldmatrix.sync.aligned.m8n8.x4.shared.b16 {%0,%1,%2,%3}, [%4];"
                 : "=r"(r0), "=r"(r1), "=r"(r2), "=r"(r3) : "r"(addr));
}
__device__ __forceinline__ void mma16816(float* d, const uint32_t* a, const uint32_t* b) {
    asm volatile(
        "mma.sync.aligned.m16n8k16.row.col.f32.f16.f16.f32 "
        "{%0,%1,%2,%3}, {%4,%5,%6,%7}, {%8,%9}, {%0,%1,%2,%3};"
        : "+f"(d[0]), "+f"(d[1]), "+f"(d[2]), "+f"(d[3])
        : "r"(a[0]), "r"(a[1]), "r"(a[2]), "r"(a[3]), "r"(b[0]), "r"(b[1]));
}
#define CP16(dst, src) \
    asm volatile("cp.async.cg.shared.global [%0], [%1], 16;" :: "r"(dst), "l"(src))
#define CP_COMMIT() asm volatile("cp.async.commit_group;" ::: "memory")
#define CP_WAIT(n)  asm volatile("cp.async.wait_group %0;" :: "n"(n) : "memory")

// ---------------- pad fmess ---------------------------------------------------
__global__ void pad_fmess(const float* __restrict__ fmess) {
    int i = blockIdx.x * blockDim.x + threadIdx.x;
    if (i >= N_MSG * KQ) return;
    int n = i / KQ, c = i % KQ;
    float x = (c < IN_F) ? fmess[n * IN_F + c] : 0.0f;
    g_f16[i] = __float2half_rn(x);
}

// ---------------- weight packing --------------------------------------------
__global__ void pack_all(const float* __restrict__ Wq, const float* __restrict__ bq,
                         const float* __restrict__ Wk, const float* __restrict__ bk,
                         const float* __restrict__ Wv, const float* __restrict__ bv,
                         const float* __restrict__ Wz, const float* __restrict__ bz,
                         const float* __restrict__ Wr, const float* __restrict__ Ur,
                         const float* __restrict__ bur,
                         const float* __restrict__ Wh, const float* __restrict__ bh) {
    int i = blockIdx.x * blockDim.x + threadIdx.x;
    const int WIDE = IN_F + H;  // 391
    if (i < 512 * H) {
        int n = i / H, k = i % H;
        float kv = (n < H) ? Wk[n * H + k] : Wv[(n - H) * H + k];
        g_Wkv16[i] = __float2half_rn(kv);
        float zr = (n < H) ? Wz[n * WIDE + IN_F + k] : Ur[(n - H) * H + k];
        g_Wzr16[i] = __float2half_rn(zr);
    }
    if (i < H * H) {
        int n = i / H, k = i % H;
        g_Wh216[i] = __float2half_rn(Wh[n * WIDE + IN_F + k]);
    }
    if (i < 1024 * KQ) {
        int n = i / KQ, k = i % KQ;
        float v = 0.0f;
        if (k < IN_F) {
            if (n < 256) v = Wz[n * WIDE + k];
            else if (n < 512) v = Wr[(n - 256) * IN_F + k];
            else if (n < 768) v = Wh[(n - 512) * WIDE + k];
            else v = Wq[(n - 768) * IN_F + k];
        }
        g_Wpre16[i] = __float2half_rn(v);
    }
    if (i < 512) g_bkv[i] = (i < 256) ? bk[i] : bv[i - 256];
    if (i < 1024) {
        float b = (i < 256) ? bz[i] : (i < 512) ? bur[i - 256]
                : (i < 768) ? bh[i - 512] : bq[i - 768];
        g_bpre[i] = b;
    }
}

// ---------------- step-0 rank-1 kernels --------------------------------------
__global__ void bv_t_kernel(const float* __restrict__ Wz, const float* __restrict__ Ur,
                            const float* __restrict__ bv) {
    const int WIDE = IN_F + H;
    int o = blockIdx.x * 8 + (threadIdx.x >> 5);
    int lane = threadIdx.x & 31;
    float s = 0.f;
#pragma unroll
    for (int t = 0; t < 8; t++) {
        int k = lane + 32 * t;
        float w = (o < 256) ? Wz[o * WIDE + IN_F + k] : Ur[(o - 256) * H + k];
        s += bv[k] * w;
    }
    for (int d = 16; d; d >>= 1) s += __shfl_xor_sync(0xffffffffu, s, d);
    if (lane == 0) g_tzr[o] = s;
}

__global__ void zr0_kernel(const float* __restrict__ bv) {
    int i = blockIdx.x * blockDim.x + threadIdx.x;   // over N*H
    int n = i >> 8, c = i & 255;
    float b = bv[c];
    g_sumh[i] = b;
    g_z[i] = sigmoidf_(g_F[(size_t)n * 768 + c] + g_tzr[c]);
    float rv = sigmoidf_(g_F[(size_t)n * 768 + 256 + c] + g_tzr[256 + c]) * b;
    g_rs16[i] = __float2half_rn(rv);
}

// ---------------- mma.sync GEMM: 128x128 tile, single-pass fp16 --------------
#define GT_PRE 0
#define GT_KV 1
#define GT_ZR 2
#define GT_FINAL 3
#define STR 40                  // padded smem row stride (fp16); conflict-free
#define STAGEB (128 * STR * 2)  // 10240 bytes per stage per operand
#define SMEM_DYN (8 * STAGEB)   // 4 stages x (A + B)

__global__ __launch_bounds__(256, 2)
void gemm_mma(const __half* __restrict__ Aw, const __half* __restrict__ Bw,
              const float* __restrict__ bias, int Kp, int mode, float* __restrict__ dst) {
    extern __shared__ __half dsm[];
    const uint32_t sA0 = smem_u32(dsm);
    const uint32_t sB0 = sA0 + 4 * STAGEB;

    const int tid = threadIdx.x, lane = tid & 31, wid = tid >> 5;
    const int wm = (wid & 1) * 64, wn = (wid >> 1) * 32;
    const int row0 = blockIdx.y * 128, col0 = blockIdx.x * 128;

    const int arow = wm + (lane & 15), ak = (lane >> 4) << 3;
    const int g = lane >> 3;
    const int brow = wn + ((g >> 1) << 3) + (lane & 7), bk = (g & 1) << 3;
    const uint32_t aoff_l = (uint32_t)(arow * STR + ak) * 2;
    const uint32_t boff_l = (uint32_t)(brow * STR + bk) * 2;

    const int NC = Kp >> 5;     // single pass over K

    auto issue = [&](int c) {
        int kk = c << 5;
        const uint32_t abase = sA0 + (uint32_t)(c & 3) * STAGEB;
        const uint32_t bbase = sB0 + (uint32_t)(c & 3) * STAGEB;
#pragma unroll
        for (int i = 0; i < 2; i++) {
            int t2 = tid + (i << 8);
            int row = t2 >> 2, coli = (t2 & 3) << 3;
            uint32_t so = (uint32_t)(row * STR + coli) * 2;
            CP16(abase + so, Aw + (size_t)(row0 + row) * Kp + kk + coli);
            CP16(bbase + so, Bw + (size_t)(col0 + row) * Kp + kk + coli);
        }
        CP_COMMIT();
    };

    float acc[4][4][4];
#pragma unroll
    for (int i = 0; i < 4; i++)
#pragma unroll
        for (int j = 0; j < 4; j++)
#pragma unroll
            for (int q = 0; q < 4; q++) acc[i][j][q] = 0.f;

    issue(0); issue(1); issue(2);

    for (int c = 0; c < NC; c++) {
        const int allowed = NC - 1 - c;
        if (allowed >= 2)      CP_WAIT(2);
        else if (allowed == 1) CP_WAIT(1);
        else                   CP_WAIT(0);
        __syncthreads();
        if (c + 3 < NC) issue(c + 3);

        const uint32_t abase = sA0 + (uint32_t)(c & 3) * STAGEB + aoff_l;
        const uint32_t bbase = sB0 + (uint32_t)(c & 3) * STAGEB + boff_l;
#pragma unroll
        for (int kk2 = 0; kk2 < 2; kk2++) {
            uint32_t a[4][4], bf[4][2];
#pragma unroll
            for (int mt = 0; mt < 4; mt++)
                ldsm_x4(a[mt][0], a[mt][1], a[mt][2], a[mt][3],
                        abase + mt * 16 * STR * 2 + kk2 * 32);
#pragma unroll
            for (int np = 0; np < 2; np++)
                ldsm_x4(bf[2 * np][0], bf[2 * np][1], bf[2 * np + 1][0], bf[2 * np + 1][1],
                        bbase + np * 16 * STR * 2 + kk2 * 32);
#pragma unroll
            for (int mt = 0; mt < 4; mt++)
#pragma unroll
                for (int nt = 0; nt < 4; nt++)
                    mma16816(acc[mt][nt], a[mt], bf[nt]);
        }
    }

    // ---------------- fused epilogue ----------------
    auto apply = [&](int r, int c, float v0, float v1) {
        if (mode == GT_PRE) {
            v0 += bias[c]; v1 += bias[c + 1];
            if (c < 768) {
                g_F[(size_t)r * 768 + c] = v0;
                g_F[(size_t)r * 768 + c + 1] = v1;
            } else {
                g_P[(size_t)r * 256 + c - 768] = v0;
                g_P[(size_t)r * 256 + c - 767] = v1;
            }
        } else if (mode == GT_KV) {
            dst[(size_t)r * 512 + c] = v0 + bias[c];
            dst[(size_t)r * 512 + c + 1] = v1 + bias[c + 1];
        } else if (mode == GT_ZR) {
            if (c < 256) {
                g_z[(size_t)r * 256 + c] = sigmoidf_(g_F[(size_t)r * 768 + c] + v0);
                g_z[(size_t)r * 256 + c + 1] = sigmoidf_(g_F[(size_t)r * 768 + c + 1] + v1);
            } else {
                int cc = c - 256;
                float rv0 = sigmoidf_(g_F[(size_t)r * 768 + 256 + cc] + v0) *
                            g_sumh[(size_t)r * 256 + cc];
                float rv1 = sigmoidf_(g_F[(size_t)r * 768 + 257 + cc] + v1) *
                            g_sumh[(size_t)r * 256 + cc + 1];
                g_rs16[(size_t)r * 256 + cc] = __float2half_rn(rv0);
                g_rs16[(size_t)r * 256 + cc + 1] = __float2half_rn(rv1);
            }
        } else {  // GT_FINAL
            float pre0 = tanhf(g_F[(size_t)r * 768 + 512 + c] + v0);
            float pre1 = tanhf(g_F[(size_t)r * 768 + 513 + c] + v1);
            float z0 = g_z[(size_t)r * 256 + c], z1 = g_z[(size_t)r * 256 + c + 1];
            float s0 = g_sumh[(size_t)r * 256 + c], s1 = g_sumh[(size_t)r * 256 + c + 1];
            float nh0 = (1.0f - z0) * s0 + z0 * pre0;
            float nh1 = (1.0f - z1) * s1 + z1 * pre1;
            if (r == 0) { nh0 = 0.0f; nh1 = 0.0f; }
            dst[(size_t)r * 256 + c] = nh0;
            dst[(size_t)r * 256 + c + 1] = nh1;
            g_h16[(size_t)r * 256 + c] = __float2half_rn(nh0);
            g_h16[(size_t)r * 256 + c + 1] = __float2half_rn(nh1);
        }
    };

#pragma unroll
    for (int mt = 0; mt < 4; mt++) {
#pragma unroll
        for (int nt = 0; nt < 4; nt++) {
            int r = row0 + wm + mt * 16 + (lane >> 2);
            int c = col0 + wn + nt * 8 + ((lane & 3) << 1);
            apply(r, c, acc[mt][nt][0], acc[mt][nt][1]);
            apply(r + 8, c, acc[mt][nt][2], acc[mt][nt][3]);
        }
    }
}

// ---------------- qscore ------------------------------------------------------
__global__ void qscore_kernel(const float* __restrict__ alpha) {
    int warp = threadIdx.x >> 5, lane = threadIdx.x & 31;
    int n = blockIdx.x * 8 + warp;
    float acc[4] = {0.f, 0.f, 0.f, 0.f};
#pragma unroll
    for (int tt = 0; tt < 8; tt++) {
        int c = lane + 32 * tt;
        float v = g_P[(size_t)n * H + c];
        float lr = v >= 0.f ? v : 0.01f * v;
        acc[tt >> 1] += lr * alpha[(tt >> 1) * 128 + (c & 63)];
    }
#pragma unroll
    for (int hh = 0; hh < 4; hh++)
        for (int o = 16; o; o >>= 1)
            acc[hh] += __shfl_xor_sync(0xffffffffu, acc[hh], o);
    if (lane == 0) {
#pragma unroll
        for (int hh = 0; hh < 4; hh++) g_qs[n * 4 + hh] = acc[hh];
    }
}

// ---------------- per-step: kscore + rowsum(h) -------------------------------
__global__ void prep_kernel(const float* __restrict__ alpha) {
    int warp = threadIdx.x >> 5, lane = threadIdx.x & 31;
    int n = blockIdx.x * 8 + warp;
    float rs = 0.f;
    float acc[4] = {0.f, 0.f, 0.f, 0.f};
#pragma unroll
    for (int tt = 0; tt < 8; tt++) {
        int c = lane + 32 * tt;
        rs += g_h[(size_t)n * H + c];
        float v = g_KV[(size_t)n * 512 + c];
        float lr = v >= 0.f ? v : 0.01f * v;
        acc[tt >> 1] += lr * alpha[(tt >> 1) * 128 + 64 + (c & 63)];
    }
    for (int o = 16; o; o >>= 1) {
        rs += __shfl_xor_sync(0xffffffffu, rs, o);
#pragma unroll
        for (int hh = 0; hh < 4; hh++)
            acc[hh] += __shfl_xor_sync(0xffffffffu, acc[hh], o);
    }
    if (lane == 0) {
        g_rowsum[n] = rs;
#pragma unroll
        for (int hh = 0; hh < 4; hh++) g_ks[n * 4 + hh] = acc[hh];
    }
}

// ---------------- attention ---------------------------------------------------
__global__ __launch_bounds__(256)
void attn_kernel(const int* __restrict__ bgraph, const float* __restrict__ abias) {
    int n = blockIdx.x;
    int t = threadIdx.x;
    __shared__ int js[NNB];
    __shared__ float sc[NNB][HEADS];
    __shared__ float wgt[NNB][HEADS];
    if (t < NNB) js[t] = bgraph[n * NNB + t];
    __syncthreads();
    if (t < NNB * HEADS) {
        int m = t >> 2, hh = t & 3;
        int j = js[m];
        float s = g_qs[n * 4 + hh] + g_ks[j * 4 + hh] + abias[hh];
        if (g_rowsum[j] == 0.0f) s = NEG_INF;
        sc[m][hh] = s;
    }
    __syncthreads();
    if (t < HEADS) {
        float mx = -INFINITY;
#pragma unroll
        for (int m = 0; m < NNB; m++) mx = fmaxf(mx, sc[m][t]);
        float e[NNB], ssum = 0.f;
#pragma unroll
        for (int m = 0; m < NNB; m++) { e[m] = expf(sc[m][t] - mx); ssum += e[m]; }
        float inv = 1.0f / ssum;
#pragma unroll
        for (int m = 0; m < NNB; m++) wgt[m][t] = e[m] * inv;
    }
    __syncthreads();
    int hh = t >> 6;
    float acc = 0.f;
#pragma unroll
    for (int m = 0; m < NNB; m++)
        acc += wgt[m][hh] * g_KV[(size_t)js[m] * 512 + 256 + t];
    size_t idx = (size_t)n * H + t;
    g_sumh[idx] = acc;
    g_sh16[idx] = __float2half_rn(acc);
}

// ---------------- launch -------------------------------------------------------
static void* symaddr(const void* s) {
    void* p = nullptr;
    cudaGetSymbolAddress(&p, s);
    return p;
}

extern "C" void kernel_launch(void* const* d_in, const int* in_sizes, int n_in,
                              void* d_out, int out_size) {
    const float* fmess = (const float*)d_in[0];
    const int*   bgraph = (const int*)d_in[1];
    const float* Wq = (const float*)d_in[2];
    const float* bq = (const float*)d_in[3];
    const float* Wk = (const float*)d_in[4];
    const float* bk = (const float*)d_in[5];
    const float* Wv = (const float*)d_in[6];
    const float* bv = (const float*)d_in[7];
    const float* alpha = (const float*)d_in[8];
    const float* abias = (const float*)d_in[9];
    const float* Wz = (const float*)d_in[10];
    const float* bz = (const float*)d_in[11];
    const float* Wr = (const float*)d_in[12];
    const float* Ur = (const float*)d_in[13];
    const float* bur = (const float*)d_in[14];
    const float* Wh = (const float*)d_in[15];
    const float* bh = (const float*)d_in[16];
    float* out = (float*)d_out;

    float* p_h  = (float*)symaddr(g_h);
    float* p_KV = (float*)symaddr(g_KV);
    const __half* a_h16  = (const __half*)symaddr(g_h16);
    const __half* a_sh16 = (const __half*)symaddr(g_sh16);
    const __half* a_rs16 = (const __half*)symaddr(g_rs16);
    const __half* a_f16  = (const __half*)symaddr(g_f16);
    const __half* w_kv   = (const __half*)symaddr(g_Wkv16);
    const __half* w_zr   = (const __half*)symaddr(g_Wzr16);
    const __half* w_h2   = (const __half*)symaddr(g_Wh216);
    const __half* w_pr   = (const __half*)symaddr(g_Wpre16);
    const float* b_kv  = (const float*)symaddr(g_bkv);
    const float* b_pre = (const float*)symaddr(g_bpre);

    cudaFuncSetAttribute(gemm_mma, cudaFuncAttributeMaxDynamicSharedMemorySize, SMEM_DYN);

    pad_fmess<<<(N_MSG * KQ + 255) / 256, 256>>>(fmess);
    pack_all<<<(1024 * KQ + 255) / 256, 256>>>(Wq, bq, Wk, bk, Wv, bv, Wz, bz,
                                               Wr, Ur, bur, Wh, bh);

    // PRE: [F(768) | Qpre(256)] = fmess @ Wpre^T + bpre
    gemm_mma<<<dim3(8, 128), 256, SMEM_DYN>>>(a_f16, w_pr, b_pre, KQ, GT_PRE, nullptr);
    qscore_kernel<<<N_MSG / 8, 256>>>(alpha);

    // ---- step 0 (exact rank-1 shortcut: h=0 => sum_h = bv for every row) ----
    bv_t_kernel<<<64, 256>>>(Wz, Ur, bv);
    zr0_kernel<<<N_MSG * H / 256, 256>>>(bv);
    gemm_mma<<<dim3(2, 128), 256, SMEM_DYN>>>(a_rs16, w_h2, nullptr, H, GT_FINAL, p_h);

    // ---- steps 1..DEPTH-1 ----
    for (int step = 1; step < DEPTH; step++) {
        gemm_mma<<<dim3(4, 128), 256, SMEM_DYN>>>(a_h16, w_kv, b_kv, H, GT_KV, p_KV);
        prep_kernel<<<N_MSG / 8, 256>>>(alpha);
        attn_kernel<<<N_MSG, 256>>>(bgraph, abias);
        gemm_mma<<<dim3(4, 128), 256, SMEM_DYN>>>(a_sh16, w_zr, nullptr, H, GT_ZR, nullptr);
        gemm_mma<<<dim3(2, 128), 256, SMEM_DYN>>>(a_rs16, w_h2, nullptr, H, GT_FINAL,
                                                  step == DEPTH - 1 ? out : p_h);
    }
    (void)in_sizes; (void)n_in; (void)out_size;
}